// round 13
// baseline (speedup 1.0000x reference)
#include <cuda_runtime.h>
#include <cstdint>
#include <math.h>

// BaseSmear: project 64^3 grid points into 8 camera images, nearest-neighbor
// gather of 32 feature channels + depth + validity + ray direction.
//
//   Pipelined coarse-grained: per-image transposes on stream A overlapped
//   with TWO smear chunks {2 images, 6 images} on stream B (coarse chunks
//   avoid the wave-quantization tax that killed per-image pipelining).
//
//   smear: per-thread projection; cooperative gather (8 lanes share one
//   pixel's 128B channel vector, offsets via SHFL) with all 8 LDG.128
//   hoisted (MLP=8); extras stored inside the latency window; warp-local
//   swizzled smem stage; STG.128 + __stcs streaming output.

#define II 8
#define CC 32
#define HH 240
#define WW 320
#define HW (HH*WW)          // 76800
#define NN (64*64*64)       // 262144
#define NN4 (NN/4)          // 65536

__device__ float g_imgT[(size_t)II * HW * CC];   // 78.6 MB channels-last scratch

// ---- transpose one image: [C, HW] -> [HW, C] --------------------------------
__global__ __launch_bounds__(256) void transpose_kernel(const float* __restrict__ images,
                                                        int img) {
    __shared__ float tile[32][33];
    const int pixbase = blockIdx.x * 32;
    const int lane = threadIdx.x & 31;
    const int wy   = threadIdx.x >> 5;               // 0..7

    const float* src = images + (size_t)img * CC * HW + pixbase;
    #pragma unroll
    for (int r = 0; r < 4; r++) {
        const int c = wy + r * 8;
        tile[c][lane] = src[(size_t)c * HW + lane];
    }
    __syncthreads();
    float* dst = g_imgT + ((size_t)img * HW + pixbase) * CC;
    #pragma unroll
    for (int r = 0; r < 4; r++) {
        const int p = wy + r * 8;
        dst[(size_t)p * CC + lane] = tile[lane][p];
    }
}

// ---- smear a chunk of images starting at i0 ---------------------------------
__global__ __launch_bounds__(256, 4) void smear_kernel(
    const float* __restrict__ trans,    // [8,3,4]
    const float* __restrict__ Tcw,      // [8,4,4]
    const float* __restrict__ coords,   // [3,64,64,64]
    float* __restrict__ out,            // [8,37,N] then [3,N]
    int i0)
{
    __shared__ float s[8][32 * 32];     // 4 KB per warp

    const int tid  = threadIdx.x;
    const int lane = tid & 31;
    const int wrp  = tid >> 5;
    const int bid  = blockIdx.x;
    const int i    = i0 + (bid >> 10);       // 1024 blocks per image
    const int nb   = (bid & 1023) << 8;      // block's base point
    const int n    = nb + tid;

    // ---------- Phase A: per-thread projection ----------
    const float px = coords[n];
    const float py = coords[NN + n];
    const float pz = coords[2 * NN + n];

    const float* T = Tcw   + i * 16;
    const float* P = trans + i * 12;

    const float depth = T[8] * px + T[9] * py + T[10] * pz + T[11];
    const float w  = P[8] * px + P[9] * py + P[10] * pz + P[11];
    const float ws = (fabsf(w) < 1e-8f) ? 1e-8f : w;
    const float u  = (P[0] * px + P[1] * py + P[2] * pz + P[3]) / ws;
    const float v  = (P[4] * px + P[5] * py + P[6] * pz + P[7]) / ws;

    const bool valid = (u >= 0.0f) && (u <= (float)(WW - 1)) &&
                       (v >= 0.0f) && (v <= (float)(HH - 1)) &&
                       (depth > 0.0f);
    const float validf = valid ? 1.0f : 0.0f;

    const int ui = (int)fminf(fmaxf(rintf(u), 0.0f), (float)(WW - 1));
    const int vi = (int)fminf(fmaxf(rintf(v), 0.0f), (float)(HH - 1));
    const int poffEnc = valid ? (vi * WW + ui) : -1;

    // ---------- Phase B1: hoisted cooperative gather (MLP = 8) ----------
    const int chunk = lane & 7;              // which 16B of the 128B pixel vec
    const int ptoff = lane >> 3;             // which of 4 points this instr

    const float* imgBase = g_imgT + (size_t)i * HW * CC + chunk * 4;
    const float4 z4 = make_float4(0.f, 0.f, 0.f, 0.f);

    float4 f[8];
    #pragma unroll
    for (int it = 0; it < 8; it++) {
        const int pe = __shfl_sync(0xffffffffu, poffEnc, it * 4 + ptoff);
        f[it] = z4;
        if (pe >= 0)
            f[it] = __ldg((const float4*)(imgBase + (size_t)pe * CC));
    }

    // ---------- Phase A2: extras + coords (fills the gather latency) --------
    {
        const float ccx = -(T[0] * T[3] + T[4] * T[7] + T[8]  * T[11]);
        const float ccy = -(T[1] * T[3] + T[5] * T[7] + T[9]  * T[11]);
        const float ccz = -(T[2] * T[3] + T[6] * T[7] + T[10] * T[11]);
        float dx = px - ccx, dy = py - ccy, dz = pz - ccz;
        const float inv = 1.0f / (sqrtf(dx * dx + dy * dy + dz * dz) + 1e-8f);

        float* eo = out + (size_t)i * 37 * NN + n;
        __stcs(eo + (size_t)32 * NN, depth);
        __stcs(eo + (size_t)33 * NN, validf);
        __stcs(eo + (size_t)34 * NN, dx * inv);
        __stcs(eo + (size_t)35 * NN, dy * inv);
        __stcs(eo + (size_t)36 * NN, dz * inv);
        if (i == 0) {
            float* tail = out + (size_t)II * 37 * NN;
            __stcs(tail + n,          px);
            __stcs(tail + NN + n,     py);
            __stcs(tail + 2 * NN + n, pz);
        }
    }

    // ---------- Phase B2: drain gathers into warp-local swizzled smem -------
    const int ch = chunk * 4;
    float* sw = s[wrp];
    #pragma unroll
    for (int it = 0; it < 8; it++) {
        const int q = it * 4 + ptoff;        // point index within warp (0..31)
        const int base = ch * 32 + (q ^ (chunk * 4));
        sw[base]      = f[it].x;
        sw[base + 32] = f[it].y;
        sw[base + 64] = f[it].z;
        sw[base + 96] = f[it].w;
    }

    __syncwarp();

    // ---------- Phase C: warp-local coalesced float4 streamed output ----------
    float4* o4 = (float4*)out + (size_t)i * 37 * NN4 + (nb >> 2) + wrp * 8;
    #pragma unroll
    for (int r = 0; r < 8; r++) {
        const int c  = r * 4 + (lane >> 3);  // channel 0..31
        const int qq = lane & 7;             // float4 index within warp (0..7)
        const float4 val = *(const float4*)&sw[c * 32 + ((qq * 4) ^ (c & 28))];
        __stcs(&o4[(size_t)c * NN4 + qq], val);
    }
}

extern "C" void kernel_launch(void* const* d_in, const int* in_sizes, int n_in,
                              void* d_out, int out_size) {
    const float* images = (const float*)d_in[0];
    const float* trans  = (const float*)d_in[1];
    const float* Tcw    = (const float*)d_in[2];
    const float* coords = (const float*)d_in[3];
    float* out = (float*)d_out;

    // lazily created host-side objects (no device memory involved)
    static cudaStream_t sA = nullptr, sB = nullptr;
    static cudaEvent_t evRoot, evA, evB, evT[II];
    if (!sA) {
        cudaStreamCreateWithFlags(&sA, cudaStreamNonBlocking);
        cudaStreamCreateWithFlags(&sB, cudaStreamNonBlocking);
        cudaEventCreateWithFlags(&evRoot, cudaEventDisableTiming);
        cudaEventCreateWithFlags(&evA,    cudaEventDisableTiming);
        cudaEventCreateWithFlags(&evB,    cudaEventDisableTiming);
        for (int i = 0; i < II; i++)
            cudaEventCreateWithFlags(&evT[i], cudaEventDisableTiming);
    }

    // fork both worker streams from the launch stream
    cudaEventRecord(evRoot, 0);
    cudaStreamWaitEvent(sA, evRoot, 0);
    cudaStreamWaitEvent(sB, evRoot, 0);

    // stream A: all 8 per-image transposes
    for (int i = 0; i < II; i++) {
        transpose_kernel<<<HW / 32, 256, 0, sA>>>(images, i);
        cudaEventRecord(evT[i], sA);
    }

    // stream B: smear chunk {0,1} after evT[1]; chunk {2..7} after evT[7]
    cudaStreamWaitEvent(sB, evT[1], 0);
    smear_kernel<<<2 * (NN / 256), 256, 0, sB>>>(trans, Tcw, coords, out, 0);
    cudaStreamWaitEvent(sB, evT[7], 0);
    smear_kernel<<<6 * (NN / 256), 256, 0, sB>>>(trans, Tcw, coords, out, 2);

    // join back into the launch stream
    cudaEventRecord(evA, sA);
    cudaEventRecord(evB, sB);
    cudaStreamWaitEvent(0, evA, 0);
    cudaStreamWaitEvent(0, evB, 0);
}

// round 14
// speedup vs baseline: 1.0174x; 1.0174x over previous
#include <cuda_runtime.h>
#include <cstdint>
#include <math.h>

// BaseSmear: project 64^3 grid points into 8 camera images, nearest-neighbor
// gather of 32 feature channels + depth + validity + ray direction.
//
//   1) vectorized transpose [I,C,H,W] -> [I,H,W,C]: 32ch x 256pix tiles,
//      LDG.128/STS.128 in, scalar-LDS + STG.128 out (all conflict-free).
//   2) smear (round-11 winner): per-thread projection; cooperative gather
//      (8 lanes share one pixel's 128B channel vector, offsets via SHFL),
//      all 8 LDG.128 hoisted (MLP=8); extras stored inside the latency
//      window; warp-local swizzled smem stage; STG.128 + __stcs output.

#define II 8
#define CC 32
#define HH 240
#define WW 320
#define HW (HH*WW)          // 76800
#define NN (64*64*64)       // 262144
#define NN4 (NN/4)          // 65536

__device__ float g_imgT[(size_t)II * HW * CC];   // 78.6 MB channels-last scratch

// ---- Phase 1: vectorized [C, HW] -> [HW, C] transpose ----------------------
// block: 256 threads, tile: 32 channels x 256 pixels. grid = II * (HW/256).
__global__ __launch_bounds__(256) void transpose_kernel(const float* __restrict__ images) {
    __shared__ float s[32 * 256];                    // [ch][pix], 32 KB

    const int tilesPerImg = HW / 256;                // 300
    const int i       = blockIdx.x / tilesPerImg;
    const int pixbase = (blockIdx.x % tilesPerImg) * 256;
    const int tid = threadIdx.x;

    // load: thread -> channel c = tid>>3, float4 pixel-segments k8 + 8*r
    {
        const int c  = tid >> 3;                     // 0..31
        const int k8 = tid & 7;                      // 0..7
        const float4* src = (const float4*)(images + (size_t)i * CC * HW
                                            + (size_t)c * HW + pixbase);
        float4* srow = (float4*)&s[c * 256];
        #pragma unroll
        for (int r = 0; r < 8; r++) {
            const int k = k8 + 8 * r;                // 0..63 (float4 index)
            srow[k] = __ldcs(src + k);               // streaming read, STS.128
        }
    }
    __syncthreads();

    // store: thread -> pixel p = tid; gather 32 channels (scalar LDS,
    // row stride 256 == 0 mod 32 -> lanes hit distinct banks), STG.128 x8
    {
        const int p = tid;
        float4* dst = (float4*)(g_imgT + ((size_t)i * HW + pixbase + p) * CC);
        #pragma unroll
        for (int j = 0; j < 8; j++) {
            float4 v;
            v.x = s[(4 * j + 0) * 256 + p];
            v.y = s[(4 * j + 1) * 256 + p];
            v.z = s[(4 * j + 2) * 256 + p];
            v.w = s[(4 * j + 3) * 256 + p];
            dst[j] = v;                              // coalesced STG.128
        }
    }
}

// ---- Phase 2: project + MLP-8 coop gather + warp-local stage + STG.128 -----
__global__ __launch_bounds__(256, 4) void smear_kernel(
    const float* __restrict__ trans,    // [8,3,4]
    const float* __restrict__ Tcw,      // [8,4,4]
    const float* __restrict__ coords,   // [3,64,64,64]
    float* __restrict__ out)            // [8,37,N] then [3,N]
{
    __shared__ float s[8][32 * 32];     // 4 KB per warp

    const int tid  = threadIdx.x;
    const int lane = tid & 31;
    const int wrp  = tid >> 5;
    const int bid  = blockIdx.x;
    const int i    = bid >> 10;              // 1024 blocks per image
    const int nb   = (bid & 1023) << 8;      // block's base point
    const int n    = nb + tid;

    // ---------- Phase A: per-thread projection ----------
    const float px = coords[n];
    const float py = coords[NN + n];
    const float pz = coords[2 * NN + n];

    const float* T = Tcw   + i * 16;
    const float* P = trans + i * 12;

    const float depth = T[8] * px + T[9] * py + T[10] * pz + T[11];
    const float w  = P[8] * px + P[9] * py + P[10] * pz + P[11];
    const float ws = (fabsf(w) < 1e-8f) ? 1e-8f : w;
    const float u  = (P[0] * px + P[1] * py + P[2] * pz + P[3]) / ws;
    const float v  = (P[4] * px + P[5] * py + P[6] * pz + P[7]) / ws;

    const bool valid = (u >= 0.0f) && (u <= (float)(WW - 1)) &&
                       (v >= 0.0f) && (v <= (float)(HH - 1)) &&
                       (depth > 0.0f);
    const float validf = valid ? 1.0f : 0.0f;

    const int ui = (int)fminf(fmaxf(rintf(u), 0.0f), (float)(WW - 1));
    const int vi = (int)fminf(fmaxf(rintf(v), 0.0f), (float)(HH - 1));
    const int poffEnc = valid ? (vi * WW + ui) : -1;

    // ---------- Phase B1: hoisted cooperative gather (MLP = 8) ----------
    const int chunk = lane & 7;              // which 16B of the 128B pixel vec
    const int ptoff = lane >> 3;             // which of 4 points this instr

    const float* imgBase = g_imgT + (size_t)i * HW * CC + chunk * 4;
    const float4 z4 = make_float4(0.f, 0.f, 0.f, 0.f);

    float4 f[8];
    #pragma unroll
    for (int it = 0; it < 8; it++) {
        const int pe = __shfl_sync(0xffffffffu, poffEnc, it * 4 + ptoff);
        f[it] = z4;
        if (pe >= 0)
            f[it] = __ldg((const float4*)(imgBase + (size_t)pe * CC));
    }

    // ---------- Phase A2: extras + coords (fills the gather latency) --------
    {
        const float ccx = -(T[0] * T[3] + T[4] * T[7] + T[8]  * T[11]);
        const float ccy = -(T[1] * T[3] + T[5] * T[7] + T[9]  * T[11]);
        const float ccz = -(T[2] * T[3] + T[6] * T[7] + T[10] * T[11]);
        float dx = px - ccx, dy = py - ccy, dz = pz - ccz;
        const float inv = 1.0f / (sqrtf(dx * dx + dy * dy + dz * dz) + 1e-8f);

        float* eo = out + (size_t)i * 37 * NN + n;
        __stcs(eo + (size_t)32 * NN, depth);
        __stcs(eo + (size_t)33 * NN, validf);
        __stcs(eo + (size_t)34 * NN, dx * inv);
        __stcs(eo + (size_t)35 * NN, dy * inv);
        __stcs(eo + (size_t)36 * NN, dz * inv);
        if (i == 0) {
            float* tail = out + (size_t)II * 37 * NN;
            __stcs(tail + n,          px);
            __stcs(tail + NN + n,     py);
            __stcs(tail + 2 * NN + n, pz);
        }
    }

    // ---------- Phase B2: drain gathers into warp-local swizzled smem -------
    const int ch = chunk * 4;
    float* sw = s[wrp];
    #pragma unroll
    for (int it = 0; it < 8; it++) {
        const int q = it * 4 + ptoff;        // point index within warp (0..31)
        const int base = ch * 32 + (q ^ (chunk * 4));
        sw[base]      = f[it].x;
        sw[base + 32] = f[it].y;
        sw[base + 64] = f[it].z;
        sw[base + 96] = f[it].w;
    }

    __syncwarp();

    // ---------- Phase C: warp-local coalesced float4 streamed output ----------
    float4* o4 = (float4*)out + (size_t)i * 37 * NN4 + (nb >> 2) + wrp * 8;
    #pragma unroll
    for (int r = 0; r < 8; r++) {
        const int c  = r * 4 + (lane >> 3);  // channel 0..31
        const int qq = lane & 7;             // float4 index within warp (0..7)
        const float4 val = *(const float4*)&sw[c * 32 + ((qq * 4) ^ (c & 28))];
        __stcs(&o4[(size_t)c * NN4 + qq], val);
    }
}

extern "C" void kernel_launch(void* const* d_in, const int* in_sizes, int n_in,
                              void* d_out, int out_size) {
    const float* images = (const float*)d_in[0];
    const float* trans  = (const float*)d_in[1];
    const float* Tcw    = (const float*)d_in[2];
    const float* coords = (const float*)d_in[3];
    float* out = (float*)d_out;

    transpose_kernel<<<II * (HW / 256), 256>>>(images);
    smear_kernel<<<II * (NN / 256), 256>>>(trans, Tcw, coords, out);
}

// round 15
// speedup vs baseline: 1.2334x; 1.2123x over previous
#include <cuda_runtime.h>
#include <cstdint>
#include <math.h>

// BaseSmear: project 64^3 grid points into 8 camera images, nearest-neighbor
// gather of 32 feature channels + depth + validity + ray direction.
//
//   1) transpose [I,C,H,W] -> [I,H,W,C]: 32ch x 128pix tiles; LDG.128 in,
//      STG.128 out, BOTH sides 128B/wavefront; smem stride 129 -> all scalar
//      smem phases conflict-free.
//   2) smear (round-11/14 winner, unchanged): cooperative gather (8 lanes
//      share one pixel's 128B channel vector, offsets via SHFL), 8 LDG.128
//      hoisted (MLP=8), extras in the latency window, warp-local swizzled
//      smem stage, STG.128 + __stcs output.

#define II 8
#define CC 32
#define HH 240
#define WW 320
#define HW (HH*WW)          // 76800
#define NN (64*64*64)       // 262144
#define NN4 (NN/4)          // 65536

__device__ float g_imgT[(size_t)II * HW * CC];   // 78.6 MB channels-last scratch

// ---- Phase 1: [C, HW] -> [HW, C] transpose, 128B/wf both sides -------------
// block: 256 threads, tile: 32 channels x 128 pixels. grid = II * (HW/128).
__global__ __launch_bounds__(256) void transpose_kernel(const float* __restrict__ images) {
    __shared__ float s[32 * 129];                    // stride 129: 16.5 KB

    const int tilesPerImg = HW / 128;                // 600
    const int i       = blockIdx.x / tilesPerImg;
    const int pixbase = (blockIdx.x % tilesPerImg) * 128;
    const int t = threadIdx.x;

    // load: thread (c = t>>3, l8 = t&7), 4 x LDG.128 at float4 index l8+8r.
    // per instr: warp = 4 channels x 8 lanes x 16B = 4 x 128B lines.
    {
        const int c  = t >> 3;                       // 0..31
        const int l8 = t & 7;                        // 0..7
        const float4* src = (const float4*)(images + (size_t)i * CC * HW
                                            + (size_t)c * HW + pixbase);
        float* srow = &s[c * 129];
        #pragma unroll
        for (int r = 0; r < 4; r++) {
            const int k = l8 + 8 * r;                // float4 index 0..31
            const float4 v = __ldcs(src + k);
            // scalar STS, bank = (c + 4k + d) mod 32 -> conflict-free
            srow[4 * k + 0] = v.x;
            srow[4 * k + 1] = v.y;
            srow[4 * k + 2] = v.z;
            srow[4 * k + 3] = v.w;
        }
    }
    __syncthreads();

    // store: warp w covers pixels [16w,16w+16); lanes = (seg = lane&7,
    // pix4 = lane>>3). per instr: 4 pixels x 128B contiguous = 4 lines.
    {
        const int lane = t & 31;
        const int wrp  = t >> 5;
        const int seg  = lane & 7;                   // 16B segment of pixel vec
        const int pix4 = lane >> 3;                  // 0..3
        float4* dst = (float4*)(g_imgT + ((size_t)i * HW + pixbase) * CC) + seg;
        #pragma unroll
        for (int r = 0; r < 4; r++) {
            const int p = 16 * wrp + 4 * r + pix4;   // pixel 0..127
            float4 v;
            // LDS bank = (4*seg + d + p) mod 32 -> conflict-free
            v.x = s[(4 * seg + 0) * 129 + p];
            v.y = s[(4 * seg + 1) * 129 + p];
            v.z = s[(4 * seg + 2) * 129 + p];
            v.w = s[(4 * seg + 3) * 129 + p];
            dst[(size_t)p * 8] = v;                  // p*32 floats = p*8 float4
        }
    }
}

// ---- Phase 2: project + MLP-8 coop gather + warp-local stage + STG.128 -----
__global__ __launch_bounds__(256, 4) void smear_kernel(
    const float* __restrict__ trans,    // [8,3,4]
    const float* __restrict__ Tcw,      // [8,4,4]
    const float* __restrict__ coords,   // [3,64,64,64]
    float* __restrict__ out)            // [8,37,N] then [3,N]
{
    __shared__ float s[8][32 * 32];     // 4 KB per warp

    const int tid  = threadIdx.x;
    const int lane = tid & 31;
    const int wrp  = tid >> 5;
    const int bid  = blockIdx.x;
    const int i    = bid >> 10;              // 1024 blocks per image
    const int nb   = (bid & 1023) << 8;      // block's base point
    const int n    = nb + tid;

    // ---------- Phase A: per-thread projection ----------
    const float px = coords[n];
    const float py = coords[NN + n];
    const float pz = coords[2 * NN + n];

    const float* T = Tcw   + i * 16;
    const float* P = trans + i * 12;

    const float depth = T[8] * px + T[9] * py + T[10] * pz + T[11];
    const float w  = P[8] * px + P[9] * py + P[10] * pz + P[11];
    const float ws = (fabsf(w) < 1e-8f) ? 1e-8f : w;
    const float u  = (P[0] * px + P[1] * py + P[2] * pz + P[3]) / ws;
    const float v  = (P[4] * px + P[5] * py + P[6] * pz + P[7]) / ws;

    const bool valid = (u >= 0.0f) && (u <= (float)(WW - 1)) &&
                       (v >= 0.0f) && (v <= (float)(HH - 1)) &&
                       (depth > 0.0f);
    const float validf = valid ? 1.0f : 0.0f;

    const int ui = (int)fminf(fmaxf(rintf(u), 0.0f), (float)(WW - 1));
    const int vi = (int)fminf(fmaxf(rintf(v), 0.0f), (float)(HH - 1));
    const int poffEnc = valid ? (vi * WW + ui) : -1;

    // ---------- Phase B1: hoisted cooperative gather (MLP = 8) ----------
    const int chunk = lane & 7;              // which 16B of the 128B pixel vec
    const int ptoff = lane >> 3;             // which of 4 points this instr

    const float* imgBase = g_imgT + (size_t)i * HW * CC + chunk * 4;
    const float4 z4 = make_float4(0.f, 0.f, 0.f, 0.f);

    float4 f[8];
    #pragma unroll
    for (int it = 0; it < 8; it++) {
        const int pe = __shfl_sync(0xffffffffu, poffEnc, it * 4 + ptoff);
        f[it] = z4;
        if (pe >= 0)
            f[it] = __ldg((const float4*)(imgBase + (size_t)pe * CC));
    }

    // ---------- Phase A2: extras + coords (fills the gather latency) --------
    {
        const float ccx = -(T[0] * T[3] + T[4] * T[7] + T[8]  * T[11]);
        const float ccy = -(T[1] * T[3] + T[5] * T[7] + T[9]  * T[11]);
        const float ccz = -(T[2] * T[3] + T[6] * T[7] + T[10] * T[11]);
        float dx = px - ccx, dy = py - ccy, dz = pz - ccz;
        const float inv = 1.0f / (sqrtf(dx * dx + dy * dy + dz * dz) + 1e-8f);

        float* eo = out + (size_t)i * 37 * NN + n;
        __stcs(eo + (size_t)32 * NN, depth);
        __stcs(eo + (size_t)33 * NN, validf);
        __stcs(eo + (size_t)34 * NN, dx * inv);
        __stcs(eo + (size_t)35 * NN, dy * inv);
        __stcs(eo + (size_t)36 * NN, dz * inv);
        if (i == 0) {
            float* tail = out + (size_t)II * 37 * NN;
            __stcs(tail + n,          px);
            __stcs(tail + NN + n,     py);
            __stcs(tail + 2 * NN + n, pz);
        }
    }

    // ---------- Phase B2: drain gathers into warp-local swizzled smem -------
    const int ch = chunk * 4;
    float* sw = s[wrp];
    #pragma unroll
    for (int it = 0; it < 8; it++) {
        const int q = it * 4 + ptoff;        // point index within warp (0..31)
        const int base = ch * 32 + (q ^ (chunk * 4));
        sw[base]      = f[it].x;
        sw[base + 32] = f[it].y;
        sw[base + 64] = f[it].z;
        sw[base + 96] = f[it].w;
    }

    __syncwarp();

    // ---------- Phase C: warp-local coalesced float4 streamed output ----------
    float4* o4 = (float4*)out + (size_t)i * 37 * NN4 + (nb >> 2) + wrp * 8;
    #pragma unroll
    for (int r = 0; r < 8; r++) {
        const int c  = r * 4 + (lane >> 3);  // channel 0..31
        const int qq = lane & 7;             // float4 index within warp (0..7)
        const float4 val = *(const float4*)&sw[c * 32 + ((qq * 4) ^ (c & 28))];
        __stcs(&o4[(size_t)c * NN4 + qq], val);
    }
}

extern "C" void kernel_launch(void* const* d_in, const int* in_sizes, int n_in,
                              void* d_out, int out_size) {
    const float* images = (const float*)d_in[0];
    const float* trans  = (const float*)d_in[1];
    const float* Tcw    = (const float*)d_in[2];
    const float* coords = (const float*)d_in[3];
    float* out = (float*)d_out;

    transpose_kernel<<<II * (HW / 128), 256>>>(images);
    smear_kernel<<<II * (NN / 256), 256>>>(trans, Tcw, coords, out);
}